// round 16
// baseline (speedup 1.0000x reference)
#include <cuda_runtime.h>
#include <cuda_fp16.h>
#include <math.h>

#define Bb 4
#define Gg 128
#define Nn 2048
#define Pp 4
#define Ff 64
#define BP 16
#define ZTOL 1e-9f
#define NCH 128
#define CHR 16
#define MAXNNZ (1 << 19)
#define MAXE 256

__device__ __align__(16) __half2 g_Wxh[BP * Nn * (Ff / 2)];
__device__ __align__(16) float4  g_T1n[Nn * BP + BP];
__device__ __align__(16) float4  g_T2n[Nn * BP];
__device__ float g_s2p[BP * Nn];
__device__ __align__(16) float g_s1q[4 * BP * Nn];   // f-quarter partials
__device__ __align__(16) float g_s2q[4 * BP * Nn];
__device__ __align__(16) int g_cnt[Nn * NCH];
__device__ __align__(16) int g_off2[Nn * NCH];
__device__ int   g_tot[Nn];
__device__ int   g_colptr[Nn + 1];
__device__ __align__(16) float2 g_rv[MAXNNZ];
__device__ __align__(16) float  g_yT[BP * Nn * Ff];  // [bp][n][f] 8MB

// ---------------------------------------------------------------------------
// K1 (f-split x4, n-blocked x4): block = (fq, nch, p, b); 16 f x 1024 n per
// block, 4 n per thread. Each smem W value feeds 4 FMAs -> LDS traffic /4.
// ---------------------------------------------------------------------------
__global__ void k1_wx(const float* __restrict__ x, const float* __restrict__ a,
                      const float* __restrict__ W) {
    const int bx = blockIdx.x;            // 0..7: fq = bx>>1, nch = bx&1
    const int fq = bx >> 1;
    const int b = blockIdx.z, p = blockIdx.y;
    const int n0 = (bx & 1) * 1024 + threadIdx.x * 4;

    __shared__ __align__(16) float Ws[Gg * 16];      // [g][16f] 8KB
    __shared__ float as1[16], as2[16];

    for (int i = threadIdx.x; i < Gg * 16; i += 256) {
        int fl = i >> 7, g = i & 127;
        Ws[g * 16 + fl] = W[(p * Ff + fq * 16 + fl) * Gg + g];
    }
    if (threadIdx.x < 16) {
        as1[threadIdx.x] = a[p * 2 * Ff + fq * 16 + threadIdx.x];
        as2[threadIdx.x] = a[p * 2 * Ff + Ff + fq * 16 + threadIdx.x];
    }
    __syncthreads();

    float accf[16][4];
#pragma unroll
    for (int fl = 0; fl < 16; fl++)
#pragma unroll
        for (int j = 0; j < 4; j++) accf[fl][j] = 0.f;

    const float* xb = x + ((size_t)b * Gg) * Nn + n0;
    const float4* Ws4 = (const float4*)Ws;

    for (int g = 0; g < Gg; g++) {
        float4 xv = *(const float4*)(xb + (size_t)g * Nn);
#pragma unroll
        for (int i = 0; i < 4; i++) {
            float4 w = Ws4[g * 4 + i];
            accf[4*i+0][0] += w.x * xv.x; accf[4*i+0][1] += w.x * xv.y;
            accf[4*i+0][2] += w.x * xv.z; accf[4*i+0][3] += w.x * xv.w;
            accf[4*i+1][0] += w.y * xv.x; accf[4*i+1][1] += w.y * xv.y;
            accf[4*i+1][2] += w.y * xv.z; accf[4*i+1][3] += w.y * xv.w;
            accf[4*i+2][0] += w.z * xv.x; accf[4*i+2][1] += w.z * xv.y;
            accf[4*i+2][2] += w.z * xv.z; accf[4*i+2][3] += w.z * xv.w;
            accf[4*i+3][0] += w.w * xv.x; accf[4*i+3][1] += w.w * xv.y;
            accf[4*i+3][2] += w.w * xv.z; accf[4*i+3][3] += w.w * xv.w;
        }
    }

    const int bp = b * Pp + p;
    float s1v[4], s2v[4];
#pragma unroll
    for (int j = 0; j < 4; j++) {
        const int n = n0 + j;
        uint4 pk;
        __half2 h;
        h = __floats2half2_rn(accf[0][j], accf[1][j]);
        pk.x = *(unsigned*)&h;
        h = __floats2half2_rn(accf[2][j], accf[3][j]);
        pk.x |= 0;  // keep layout explicit below
        // pack 16 f -> 8 half2 -> uint4 (pairs 0..3) + uint4 (pairs 4..7)
        unsigned u[8];
#pragma unroll
        for (int i = 0; i < 8; i++) {
            __half2 hh = __floats2half2_rn(accf[2*i][j], accf[2*i+1][j]);
            u[i] = *(unsigned*)&hh;
        }
        uint4* dst = (uint4*)(g_Wxh + ((size_t)(bp * Nn + n)) * (Ff / 2) + fq * 8);
        dst[0] = make_uint4(u[0], u[1], u[2], u[3]);
        dst[1] = make_uint4(u[4], u[5], u[6], u[7]);

        float s1 = 0.f, s2 = 0.f;
#pragma unroll
        for (int fl = 0; fl < 16; fl++) {
            s1 += as1[fl] * accf[fl][j];
            s2 += as2[fl] * accf[fl][j];
        }
        s1v[j] = s1; s2v[j] = s2;
    }
    *(float4*)&g_s1q[(fq * BP + bp) * Nn + n0] = make_float4(s1v[0], s1v[1], s1v[2], s1v[3]);
    *(float4*)&g_s2q[(fq * BP + bp) * Nn + n0] = make_float4(s2v[0], s2v[1], s2v[2], s2v[3]);
}

// Sum the 4 f-quarter partials; emit s2 plane + T1 exp table.
__global__ void k1_reduce() {
    const int idx = blockIdx.x * 256 + threadIdx.x;  // bp*Nn + n
    float s1 = 0.f, s2 = 0.f;
#pragma unroll
    for (int q = 0; q < 4; q++) {
        s1 += g_s1q[q * BP * Nn + idx];
        s2 += g_s2q[q * BP * Nn + idx];
    }
    const int bp = idx >> 11, n = idx & (Nn - 1);
    g_s2p[idx] = s2;
    g_T1n[n * BP + bp] = make_float4(s1, __expf(s1), __expf(0.2f * s1), 0.f);
}

// ---------------------------------------------------------------------------
// K2: ballot-compressed denominators (MUFU-free hot loop via T1 table).
// ---------------------------------------------------------------------------
__global__ void k2_rowstats(const float* __restrict__ S) {
    const int m = blockIdx.x;
    const int tid = threadIdx.x;
    const int w = tid >> 5, lane = tid & 31;

    __shared__ float red[8][BP];

    const float s2l = g_s2p[(lane & 15) * Nn + m];
    const float eas = __expf(s2l);
    const float ebs = __expf(0.2f * s2l);
    float D = 0.f;
    const float4* row4 = (const float4*)(S + (size_t)m * Nn);

#pragma unroll
    for (int seg = 0; seg < 2; seg++) {
        const int base = (seg * 8 + w) * 128;
        float4 v = row4[base / 4 + lane];
        int dn = m - (base + 4 * lane);
        if (dn == 0) v.x += 1.f; else if (dn == 1) v.y += 1.f;
        else if (dn == 2) v.z += 1.f; else if (dn == 3) v.w += 1.f;
        unsigned bm[4];
        bm[0] = __ballot_sync(0xffffffffu, fabsf(v.x) > ZTOL);
        bm[1] = __ballot_sync(0xffffffffu, fabsf(v.y) > ZTOL);
        bm[2] = __ballot_sync(0xffffffffu, fabsf(v.z) > ZTOL);
        bm[3] = __ballot_sync(0xffffffffu, fabsf(v.w) > ZTOL);
#pragma unroll
        for (int k = 0; k < 4; k++) {
            unsigned msk = bm[k];
            while (msk) {
                int j = __ffs(msk) - 1;
                msk &= msk - 1;
                int ne = base + 4 * j + k;
                float4 t1 = g_T1n[ne * BP + lane];
                float t = s2l + t1.x;
                D += (t >= 0.f) ? eas * t1.y : ebs * t1.z;
            }
        }
    }

    if (lane < BP) red[w][lane] = D;
    __syncthreads();
    if (tid < BP) {
        float d = 0.f;
#pragma unroll
        for (int ww = 0; ww < 8; ww++) d += red[ww][tid];
        float ci = (d > 0.f) ? 1.f / d : 0.f;
        float s2 = g_s2p[tid * Nn + m];
        g_T2n[m * BP + tid] =
            make_float4(s2, __expf(s2) * ci, __expf(0.2f * s2) * ci, 0.f);
    }
}

// ---------------------------------------------------------------------------
// K3: deterministic CSC build.
// ---------------------------------------------------------------------------
__global__ void k3_count(const float* __restrict__ S) {
    const int cg = blockIdx.x * 256 + threadIdx.x;
    const int n0 = cg * 4;
    const int mc = blockIdx.y, m0 = mc * CHR;
    int c0 = 0, c1 = 0, c2 = 0, c3 = 0;
#pragma unroll
    for (int mm = 0; mm < CHR; mm++) {
        float4 v = *(const float4*)(S + (size_t)(m0 + mm) * Nn + n0);
        if (fabsf(v.x) > ZTOL) c0++;
        if (fabsf(v.y) > ZTOL) c1++;
        if (fabsf(v.z) > ZTOL) c2++;
        if (fabsf(v.w) > ZTOL) c3++;
    }
    g_cnt[(n0 + 0) * NCH + mc] = c0;
    g_cnt[(n0 + 1) * NCH + mc] = c1;
    g_cnt[(n0 + 2) * NCH + mc] = c2;
    g_cnt[(n0 + 3) * NCH + mc] = c3;
}

__global__ void k3_offs() {
    const int n = blockIdx.x * 8 + (threadIdx.x >> 5);
    const int lane = threadIdx.x & 31;
    int4 c = *(const int4*)&g_cnt[n * NCH + 4 * lane];
    int s = c.x + c.y + c.z + c.w;
    int v = s;
#pragma unroll
    for (int off = 1; off < 32; off <<= 1) {
        int u = __shfl_up_sync(0xffffffffu, v, off);
        if (lane >= off) v += u;
    }
    int e = v - s;
    *(int4*)&g_off2[n * NCH + 4 * lane] =
        make_int4(e, e + c.x, e + c.x + c.y, e + c.x + c.y + c.z);
    if (lane == 31) g_tot[n] = v;
}

__global__ void k3_scan() {
    __shared__ int wsum[32];
    __shared__ int woff[32];
    const int tid = threadIdx.x;
    const int w = tid >> 5, lane = tid & 31;
    int a = g_tot[2 * tid], b = g_tot[2 * tid + 1];
    int p = a + b;
    int v = p;
#pragma unroll
    for (int off = 1; off < 32; off <<= 1) {
        int u = __shfl_up_sync(0xffffffffu, v, off);
        if (lane >= off) v += u;
    }
    if (lane == 31) wsum[w] = v;
    __syncthreads();
    if (w == 0) {
        int s = wsum[lane];
        int t = s;
#pragma unroll
        for (int off = 1; off < 32; off <<= 1) {
            int u = __shfl_up_sync(0xffffffffu, t, off);
            if (lane >= off) t += u;
        }
        woff[lane] = t - s;
    }
    __syncthreads();
    int excl = woff[w] + (v - p);
    g_colptr[2 * tid]     = excl;
    g_colptr[2 * tid + 1] = excl + a;
    if (tid == 1023) g_colptr[Nn] = excl + p;
}

__global__ void k3_fill(const float* __restrict__ S) {
    const int cg = blockIdx.x * 256 + threadIdx.x;
    const int n0 = cg * 4;
    const int mc = blockIdx.y, m0 = mc * CHR;
    int o0 = g_colptr[n0 + 0] + g_off2[(n0 + 0) * NCH + mc];
    int o1 = g_colptr[n0 + 1] + g_off2[(n0 + 1) * NCH + mc];
    int o2 = g_colptr[n0 + 2] + g_off2[(n0 + 2) * NCH + mc];
    int o3 = g_colptr[n0 + 3] + g_off2[(n0 + 3) * NCH + mc];
#pragma unroll
    for (int mm = 0; mm < CHR; mm++) {
        const int m = m0 + mm;
        float4 v = *(const float4*)(S + (size_t)m * Nn + n0);
        float mo = __int_as_float(m * (Ff / 2));
        if (fabsf(v.x) > ZTOL && o0 < MAXNNZ) g_rv[o0++] = make_float2(mo, v.x);
        if (fabsf(v.y) > ZTOL && o1 < MAXNNZ) g_rv[o1++] = make_float2(mo, v.y);
        if (fabsf(v.z) > ZTOL && o2 < MAXNNZ) g_rv[o2++] = make_float2(mo, v.z);
        if (fabsf(v.w) > ZTOL && o3 < MAXNNZ) g_rv[o3++] = make_float2(mo, v.w);
    }
}

// ---------------------------------------------------------------------------
// K4 (proven): block = column n. Phase A: cooperative weights into smem.
// Phase B: warp bp streams entries. Coalesced 256B store to g_yT[bp][n][*].
// ---------------------------------------------------------------------------
__global__ void __launch_bounds__(512) k4_out() {
    __shared__ __align__(16) float2 s_rv[MAXE];
    __shared__ __align__(16) float2 s_w2[MAXE * BP];
    __shared__ __align__(16) float4 s_t1[BP];

    const int n = blockIdx.x;
    const int tid = threadIdx.x;
    const int bp = tid >> 5, lane = tid & 31;

    if (tid < BP) s_t1[tid] = g_T1n[n * BP + tid];

    const int lo = g_colptr[n], hi = g_colptr[n + 1];
    const __half2* __restrict__ wxh = g_Wxh + (size_t)bp * Nn * (Ff / 2);
    const float4* __restrict__ t2tab = g_T2n;
    const float2* __restrict__ rv = g_rv;

    float a0 = 0.f, a1 = 0.f;

    for (int base = lo; base < hi; base += MAXE) {
        const int cnt = min(hi - base, MAXE);
        if (tid < cnt) s_rv[tid] = rv[base + tid];
        __syncthreads();

        for (int idx = tid; idx < cnt * BP; idx += 512) {
            int j = idx >> 4, bpa = idx & 15;
            float2 e = s_rv[j];
            int mo = __float_as_int(e.x);
            float4 t2 = t2tab[(mo >> 1) | bpa];
            float4 t1 = s_t1[bpa];
            float t = t1.x + t2.x;
            float wgt = e.y * ((t >= 0.f) ? t1.y * t2.y : t1.z * t2.z);
            s_w2[idx] = make_float2(e.x, wgt);
        }
        __syncthreads();

        const float2* wrow = s_w2 + bp;
#pragma unroll 8
        for (int j = 0; j < cnt; j++) {
            float2 mw = wrow[j * BP];
            int mo = __float_as_int(mw.x);
            float2 wx = __half22float2(wxh[mo + lane]);
            a0 = fmaf(mw.y, wx.x, a0);
            a1 = fmaf(mw.y, wx.y, a1);
        }
        __syncthreads();
    }

    float2* yt = (float2*)(g_yT + ((size_t)bp * Nn + n) * Ff);
    yt[lane] = make_float2(fmaxf(a0, 0.f), fmaxf(a1, 0.f));
}

// ---------------------------------------------------------------------------
// K5: transpose g_yT[bp][n][f] -> out[bp*64+f][n]. 32x32 padded-smem tiles.
// ---------------------------------------------------------------------------
__global__ void k5_transpose(float* __restrict__ out) {
    __shared__ float tile[32][33];
    const int bp = blockIdx.z;
    const int f0 = blockIdx.y * 32;
    const int n0 = blockIdx.x * 32;
    const int w = threadIdx.x >> 5, lane = threadIdx.x & 31;

    const float* src = g_yT + ((size_t)bp * Nn + n0) * Ff + f0;
#pragma unroll
    for (int k = 0; k < 4; k++) {
        int r = w + 8 * k;
        tile[r][lane] = src[(size_t)r * Ff + lane];
    }
    __syncthreads();

    float* dst = out + ((size_t)bp * Ff + f0) * Nn + n0;
#pragma unroll
    for (int k = 0; k < 4; k++) {
        int r = w + 8 * k;
        dst[(size_t)r * Nn + lane] = tile[lane][r];
    }
}

// ---------------------------------------------------------------------------
// Launch order: new k1_wx at profiled slot 4.
// ---------------------------------------------------------------------------
extern "C" void kernel_launch(void* const* d_in, const int* in_sizes, int n_in,
                              void* d_out, int out_size) {
    const float* x = (const float*)d_in[0];
    const float* a = (const float*)d_in[1];
    const float* W = (const float*)d_in[2];
    const float* S = (const float*)d_in[3];
    float* out = (float*)d_out;

    k3_count<<<dim3(2, NCH), 256>>>(S);
    k3_offs<<<256, 256>>>();
    k3_scan<<<1, 1024>>>();
    k1_wx<<<dim3(8, Pp, Bb), 256>>>(x, a, W);    // 4th launch -> profiled
    k1_reduce<<<BP * Nn / 256, 256>>>();
    k3_fill<<<dim3(2, NCH), 256>>>(S);
    k2_rowstats<<<Nn, 256>>>(S);
    k4_out<<<Nn, 512>>>();
    k5_transpose<<<dim3(Nn / 32, Ff / 32, BP), 256>>>(out);
}

// round 17
// speedup vs baseline: 1.1334x; 1.1334x over previous
#include <cuda_runtime.h>
#include <cuda_fp16.h>
#include <math.h>

#define Bb 4
#define Gg 128
#define Nn 2048
#define Pp 4
#define Ff 64
#define BP 16
#define ZTOL 1e-9f
#define NCH 128
#define CHR 16
#define MAXNNZ (1 << 19)
#define MAXE 256

__device__ __align__(16) __half2 g_Wxh[BP * Nn * (Ff / 2)];
__device__ __align__(16) float4  g_T1n[Nn * BP + BP];
__device__ __align__(16) float4  g_T2n[Nn * BP];
__device__ float g_s2p[BP * Nn];
__device__ __align__(16) float g_s1q[4 * BP * Nn];   // f-quarter partials
__device__ __align__(16) float g_s2q[4 * BP * Nn];
__device__ __align__(16) int g_cnt[Nn * NCH];
__device__ __align__(16) int g_off2[Nn * NCH];
__device__ int   g_tot[Nn];
__device__ int   g_colptr[Nn + 1];
__device__ __align__(16) float2 g_rv[MAXNNZ];
__device__ __align__(16) float  g_yT[BP * Nn * Ff];  // [bp][n][f] 8MB

// ---------------------------------------------------------------------------
// K1 (f-split x4, n-blocked x2): block = (fq, nch, p, b); 16 f x 512 n per
// block, 2 n per thread. 256 blocks, 65K threads: keeps R15's occupancy while
// halving warp count (same per-warp L1 wavefronts -> half chip wavefronts).
// ---------------------------------------------------------------------------
__global__ void k1_wx(const float* __restrict__ x, const float* __restrict__ a,
                      const float* __restrict__ W) {
    const int bx = blockIdx.x;            // 0..15: fq = bx>>2, nch = bx&3
    const int fq = bx >> 2;
    const int b = blockIdx.z, p = blockIdx.y;
    const int n0 = (bx & 3) * 512 + threadIdx.x * 2;

    __shared__ __align__(16) float Ws[Gg * 16];      // [g][16f] 8KB
    __shared__ float as1[16], as2[16];

    for (int i = threadIdx.x; i < Gg * 16; i += 256) {
        int fl = i >> 7, g = i & 127;
        Ws[g * 16 + fl] = W[(p * Ff + fq * 16 + fl) * Gg + g];
    }
    if (threadIdx.x < 16) {
        as1[threadIdx.x] = a[p * 2 * Ff + fq * 16 + threadIdx.x];
        as2[threadIdx.x] = a[p * 2 * Ff + Ff + fq * 16 + threadIdx.x];
    }
    __syncthreads();

    float acc0[16], acc1[16];            // [f][n-pair]
#pragma unroll
    for (int fl = 0; fl < 16; fl++) { acc0[fl] = 0.f; acc1[fl] = 0.f; }

    const float* xb = x + ((size_t)b * Gg) * Nn + n0;
    const float4* Ws4 = (const float4*)Ws;

#pragma unroll 2
    for (int g = 0; g < Gg; g++) {
        float2 xv = *(const float2*)(xb + (size_t)g * Nn);
#pragma unroll
        for (int i = 0; i < 4; i++) {
            float4 w = Ws4[g * 4 + i];
            acc0[4*i+0] += w.x * xv.x; acc1[4*i+0] += w.x * xv.y;
            acc0[4*i+1] += w.y * xv.x; acc1[4*i+1] += w.y * xv.y;
            acc0[4*i+2] += w.z * xv.x; acc1[4*i+2] += w.z * xv.y;
            acc0[4*i+3] += w.w * xv.x; acc1[4*i+3] += w.w * xv.y;
        }
    }

    const int bp = b * Pp + p;
    // Pack + store fp16 slices, compute s1/s2 partials for both columns.
    float s1a = 0.f, s2a = 0.f, s1b = 0.f, s2b = 0.f;
    {
        unsigned u[8];
#pragma unroll
        for (int i = 0; i < 8; i++) {
            __half2 hh = __floats2half2_rn(acc0[2*i], acc0[2*i+1]);
            u[i] = *(unsigned*)&hh;
        }
        uint4* dst = (uint4*)(g_Wxh + ((size_t)(bp * Nn + n0)) * (Ff / 2) + fq * 8);
        dst[0] = make_uint4(u[0], u[1], u[2], u[3]);
        dst[1] = make_uint4(u[4], u[5], u[6], u[7]);
#pragma unroll
        for (int fl = 0; fl < 16; fl++) {
            s1a += as1[fl] * acc0[fl];
            s2a += as2[fl] * acc0[fl];
        }
    }
    {
        unsigned u[8];
#pragma unroll
        for (int i = 0; i < 8; i++) {
            __half2 hh = __floats2half2_rn(acc1[2*i], acc1[2*i+1]);
            u[i] = *(unsigned*)&hh;
        }
        uint4* dst = (uint4*)(g_Wxh + ((size_t)(bp * Nn + n0 + 1)) * (Ff / 2) + fq * 8);
        dst[0] = make_uint4(u[0], u[1], u[2], u[3]);
        dst[1] = make_uint4(u[4], u[5], u[6], u[7]);
#pragma unroll
        for (int fl = 0; fl < 16; fl++) {
            s1b += as1[fl] * acc1[fl];
            s2b += as2[fl] * acc1[fl];
        }
    }
    *(float2*)&g_s1q[(fq * BP + bp) * Nn + n0] = make_float2(s1a, s1b);
    *(float2*)&g_s2q[(fq * BP + bp) * Nn + n0] = make_float2(s2a, s2b);
}

// Sum the 4 f-quarter partials; emit s2 plane + T1 exp table.
__global__ void k1_reduce() {
    const int idx = blockIdx.x * 256 + threadIdx.x;  // bp*Nn + n
    float s1 = 0.f, s2 = 0.f;
#pragma unroll
    for (int q = 0; q < 4; q++) {
        s1 += g_s1q[q * BP * Nn + idx];
        s2 += g_s2q[q * BP * Nn + idx];
    }
    const int bp = idx >> 11, n = idx & (Nn - 1);
    g_s2p[idx] = s2;
    g_T1n[n * BP + bp] = make_float4(s1, __expf(s1), __expf(0.2f * s1), 0.f);
}

// ---------------------------------------------------------------------------
// K2: ballot-compressed denominators (MUFU-free hot loop via T1 table).
// ---------------------------------------------------------------------------
__global__ void k2_rowstats(const float* __restrict__ S) {
    const int m = blockIdx.x;
    const int tid = threadIdx.x;
    const int w = tid >> 5, lane = tid & 31;

    __shared__ float red[8][BP];

    const float s2l = g_s2p[(lane & 15) * Nn + m];
    const float eas = __expf(s2l);
    const float ebs = __expf(0.2f * s2l);
    float D = 0.f;
    const float4* row4 = (const float4*)(S + (size_t)m * Nn);

#pragma unroll
    for (int seg = 0; seg < 2; seg++) {
        const int base = (seg * 8 + w) * 128;
        float4 v = row4[base / 4 + lane];
        int dn = m - (base + 4 * lane);
        if (dn == 0) v.x += 1.f; else if (dn == 1) v.y += 1.f;
        else if (dn == 2) v.z += 1.f; else if (dn == 3) v.w += 1.f;
        unsigned bm[4];
        bm[0] = __ballot_sync(0xffffffffu, fabsf(v.x) > ZTOL);
        bm[1] = __ballot_sync(0xffffffffu, fabsf(v.y) > ZTOL);
        bm[2] = __ballot_sync(0xffffffffu, fabsf(v.z) > ZTOL);
        bm[3] = __ballot_sync(0xffffffffu, fabsf(v.w) > ZTOL);
#pragma unroll
        for (int k = 0; k < 4; k++) {
            unsigned msk = bm[k];
            while (msk) {
                int j = __ffs(msk) - 1;
                msk &= msk - 1;
                int ne = base + 4 * j + k;
                float4 t1 = g_T1n[ne * BP + lane];
                float t = s2l + t1.x;
                D += (t >= 0.f) ? eas * t1.y : ebs * t1.z;
            }
        }
    }

    if (lane < BP) red[w][lane] = D;
    __syncthreads();
    if (tid < BP) {
        float d = 0.f;
#pragma unroll
        for (int ww = 0; ww < 8; ww++) d += red[ww][tid];
        float ci = (d > 0.f) ? 1.f / d : 0.f;
        float s2 = g_s2p[tid * Nn + m];
        g_T2n[m * BP + tid] =
            make_float4(s2, __expf(s2) * ci, __expf(0.2f * s2) * ci, 0.f);
    }
}

// ---------------------------------------------------------------------------
// K3: deterministic CSC build.
// ---------------------------------------------------------------------------
__global__ void k3_count(const float* __restrict__ S) {
    const int cg = blockIdx.x * 256 + threadIdx.x;
    const int n0 = cg * 4;
    const int mc = blockIdx.y, m0 = mc * CHR;
    int c0 = 0, c1 = 0, c2 = 0, c3 = 0;
#pragma unroll
    for (int mm = 0; mm < CHR; mm++) {
        float4 v = *(const float4*)(S + (size_t)(m0 + mm) * Nn + n0);
        if (fabsf(v.x) > ZTOL) c0++;
        if (fabsf(v.y) > ZTOL) c1++;
        if (fabsf(v.z) > ZTOL) c2++;
        if (fabsf(v.w) > ZTOL) c3++;
    }
    g_cnt[(n0 + 0) * NCH + mc] = c0;
    g_cnt[(n0 + 1) * NCH + mc] = c1;
    g_cnt[(n0 + 2) * NCH + mc] = c2;
    g_cnt[(n0 + 3) * NCH + mc] = c3;
}

__global__ void k3_offs() {
    const int n = blockIdx.x * 8 + (threadIdx.x >> 5);
    const int lane = threadIdx.x & 31;
    int4 c = *(const int4*)&g_cnt[n * NCH + 4 * lane];
    int s = c.x + c.y + c.z + c.w;
    int v = s;
#pragma unroll
    for (int off = 1; off < 32; off <<= 1) {
        int u = __shfl_up_sync(0xffffffffu, v, off);
        if (lane >= off) v += u;
    }
    int e = v - s;
    *(int4*)&g_off2[n * NCH + 4 * lane] =
        make_int4(e, e + c.x, e + c.x + c.y, e + c.x + c.y + c.z);
    if (lane == 31) g_tot[n] = v;
}

__global__ void k3_scan() {
    __shared__ int wsum[32];
    __shared__ int woff[32];
    const int tid = threadIdx.x;
    const int w = tid >> 5, lane = tid & 31;
    int a = g_tot[2 * tid], b = g_tot[2 * tid + 1];
    int p = a + b;
    int v = p;
#pragma unroll
    for (int off = 1; off < 32; off <<= 1) {
        int u = __shfl_up_sync(0xffffffffu, v, off);
        if (lane >= off) v += u;
    }
    if (lane == 31) wsum[w] = v;
    __syncthreads();
    if (w == 0) {
        int s = wsum[lane];
        int t = s;
#pragma unroll
        for (int off = 1; off < 32; off <<= 1) {
            int u = __shfl_up_sync(0xffffffffu, t, off);
            if (lane >= off) t += u;
        }
        woff[lane] = t - s;
    }
    __syncthreads();
    int excl = woff[w] + (v - p);
    g_colptr[2 * tid]     = excl;
    g_colptr[2 * tid + 1] = excl + a;
    if (tid == 1023) g_colptr[Nn] = excl + p;
}

__global__ void k3_fill(const float* __restrict__ S) {
    const int cg = blockIdx.x * 256 + threadIdx.x;
    const int n0 = cg * 4;
    const int mc = blockIdx.y, m0 = mc * CHR;
    int o0 = g_colptr[n0 + 0] + g_off2[(n0 + 0) * NCH + mc];
    int o1 = g_colptr[n0 + 1] + g_off2[(n0 + 1) * NCH + mc];
    int o2 = g_colptr[n0 + 2] + g_off2[(n0 + 2) * NCH + mc];
    int o3 = g_colptr[n0 + 3] + g_off2[(n0 + 3) * NCH + mc];
#pragma unroll
    for (int mm = 0; mm < CHR; mm++) {
        const int m = m0 + mm;
        float4 v = *(const float4*)(S + (size_t)m * Nn + n0);
        float mo = __int_as_float(m * (Ff / 2));
        if (fabsf(v.x) > ZTOL && o0 < MAXNNZ) g_rv[o0++] = make_float2(mo, v.x);
        if (fabsf(v.y) > ZTOL && o1 < MAXNNZ) g_rv[o1++] = make_float2(mo, v.y);
        if (fabsf(v.z) > ZTOL && o2 < MAXNNZ) g_rv[o2++] = make_float2(mo, v.z);
        if (fabsf(v.w) > ZTOL && o3 < MAXNNZ) g_rv[o3++] = make_float2(mo, v.w);
    }
}

// ---------------------------------------------------------------------------
// K4 (proven): block = column n. Phase A: cooperative weights into smem.
// Phase B: warp bp streams entries. Coalesced 256B store to g_yT[bp][n][*].
// ---------------------------------------------------------------------------
__global__ void __launch_bounds__(512) k4_out() {
    __shared__ __align__(16) float2 s_rv[MAXE];
    __shared__ __align__(16) float2 s_w2[MAXE * BP];
    __shared__ __align__(16) float4 s_t1[BP];

    const int n = blockIdx.x;
    const int tid = threadIdx.x;
    const int bp = tid >> 5, lane = tid & 31;

    if (tid < BP) s_t1[tid] = g_T1n[n * BP + tid];

    const int lo = g_colptr[n], hi = g_colptr[n + 1];
    const __half2* __restrict__ wxh = g_Wxh + (size_t)bp * Nn * (Ff / 2);
    const float4* __restrict__ t2tab = g_T2n;
    const float2* __restrict__ rv = g_rv;

    float a0 = 0.f, a1 = 0.f;

    for (int base = lo; base < hi; base += MAXE) {
        const int cnt = min(hi - base, MAXE);
        if (tid < cnt) s_rv[tid] = rv[base + tid];
        __syncthreads();

        for (int idx = tid; idx < cnt * BP; idx += 512) {
            int j = idx >> 4, bpa = idx & 15;
            float2 e = s_rv[j];
            int mo = __float_as_int(e.x);
            float4 t2 = t2tab[(mo >> 1) | bpa];
            float4 t1 = s_t1[bpa];
            float t = t1.x + t2.x;
            float wgt = e.y * ((t >= 0.f) ? t1.y * t2.y : t1.z * t2.z);
            s_w2[idx] = make_float2(e.x, wgt);
        }
        __syncthreads();

        const float2* wrow = s_w2 + bp;
#pragma unroll 8
        for (int j = 0; j < cnt; j++) {
            float2 mw = wrow[j * BP];
            int mo = __float_as_int(mw.x);
            float2 wx = __half22float2(wxh[mo + lane]);
            a0 = fmaf(mw.y, wx.x, a0);
            a1 = fmaf(mw.y, wx.y, a1);
        }
        __syncthreads();
    }

    float2* yt = (float2*)(g_yT + ((size_t)bp * Nn + n) * Ff);
    yt[lane] = make_float2(fmaxf(a0, 0.f), fmaxf(a1, 0.f));
}

// ---------------------------------------------------------------------------
// K5: transpose g_yT[bp][n][f] -> out[bp*64+f][n]. 32x32 padded-smem tiles.
// ---------------------------------------------------------------------------
__global__ void k5_transpose(float* __restrict__ out) {
    __shared__ float tile[32][33];
    const int bp = blockIdx.z;
    const int f0 = blockIdx.y * 32;
    const int n0 = blockIdx.x * 32;
    const int w = threadIdx.x >> 5, lane = threadIdx.x & 31;

    const float* src = g_yT + ((size_t)bp * Nn + n0) * Ff + f0;
#pragma unroll
    for (int k = 0; k < 4; k++) {
        int r = w + 8 * k;
        tile[r][lane] = src[(size_t)r * Ff + lane];
    }
    __syncthreads();

    float* dst = out + ((size_t)bp * Ff + f0) * Nn + n0;
#pragma unroll
    for (int k = 0; k < 4; k++) {
        int r = w + 8 * k;
        dst[(size_t)r * Nn + lane] = tile[lane][r];
    }
}

// ---------------------------------------------------------------------------
// Launch order: k1_wx at profiled slot 4.
// ---------------------------------------------------------------------------
extern "C" void kernel_launch(void* const* d_in, const int* in_sizes, int n_in,
                              void* d_out, int out_size) {
    const float* x = (const float*)d_in[0];
    const float* a = (const float*)d_in[1];
    const float* W = (const float*)d_in[2];
    const float* S = (const float*)d_in[3];
    float* out = (float*)d_out;

    k3_count<<<dim3(2, NCH), 256>>>(S);
    k3_offs<<<256, 256>>>();
    k3_scan<<<1, 1024>>>();
    k1_wx<<<dim3(16, Pp, Bb), 256>>>(x, a, W);   // 4th launch -> profiled
    k1_reduce<<<BP * Nn / 256, 256>>>();
    k3_fill<<<dim3(2, NCH), 256>>>(S);
    k2_rowstats<<<Nn, 256>>>(S);
    k4_out<<<Nn, 512>>>();
    k5_transpose<<<dim3(Nn / 32, Ff / 32, BP), 256>>>(out);
}